// round 17
// baseline (speedup 1.0000x reference)
#include <cuda_runtime.h>

// DepthLoss3D: R14 structure (PDL zero-kernel + fused sort/query kernel),
// with ping-pong shared buffers in the cross-warp sort stages: 1 barrier per
// stage instead of 2 (write goes to the alternate buffer, so no read-fence).
//   f(x)=max(x-ds,0.2ds-x,0)-0.2ds*[x<0], x=p-pb, ds>0:
//   sum = n1*k1 - P[n1] + (T-P[n2]) - (256-n2)*k2 - 0.2ds*(256-n3)

#define N_ELEM 4096
#define NTASKS 408   // 48 diagonal + 360 pairs

__device__ __forceinline__ int elem_index(int c, int g, int m) {
    if (c == 0)      return (g << 8) + m;
    else if (c == 1) return ((m >> 4) << 8) + (g << 4) + (m & 15);
    else             return (m << 4) + g;
}

__global__ void zero_out_kernel(float* __restrict__ out) {
    if (threadIdx.x < 3) out[threadIdx.x] = 0.0f;
    cudaTriggerProgrammaticLaunchCompletion();
}

__global__ void __launch_bounds__(256) depthloss_fused(
    const float* __restrict__ pred,   // [4096,3]
    const float* __restrict__ spac,   // [3]
    float* __restrict__ out)          // [3]
{
    __shared__ float sv[256];
    __shared__ float sw[256];
    __shared__ float sp[257];
    __shared__ float red[8];

    const int t    = threadIdx.x;
    const int lane = t & 31;
    const int wid  = t >> 5;
    const int bx   = blockIdx.x;

    // Task decode: bx < 48 -> diagonal (c,g); else pair (c, a>b).
    int c, a, b;
    bool diag;
    if (bx < 48) {
        diag = true;
        c = bx >> 4;
        a = b = bx & 15;
    } else {
        diag = false;
        const int idx = bx - 48;
        c = idx / 120;
        const int pq = idx - c * 120;
        a = 1;
        while ((a + 1) * a / 2 <= pq) ++a;
        b = pq - a * (a - 1) / 2;
    }

    float v = pred[elem_index(c, b, t) * 3 + c];
    float p = diag ? 0.0f : pred[elem_index(c, a, t) * 3 + c];

    // ---- Static bitonic sort (ascending by rank t), ping-pong SM stages. ----
    const bool u2   = !(t & 2);
    const bool u4   = !(t & 4);
    const bool u8   = !(t & 8);
    const bool u16  = !(t & 16);
    const bool u32  = !(t & 32);
    const bool u64  = !(t & 64);
    const bool u128 = !(t & 128);

#define SH(J, UP) do {                                              \
        const float o_ = __shfl_xor_sync(0xffffffffu, v, (J));      \
        const bool mn_ = (((t & (J)) == 0) == (UP));                \
        v = mn_ ? fminf(v, o_) : fmaxf(v, o_);                      \
    } while (0)

    // One barrier per cross-warp stage; BUF alternates sv/sw so no trailing
    // sync is needed (reads of a buffer always precede the next write to it,
    // separated by the intervening stage's barrier).
#define SMP(J, UP, BUF) do {                                        \
        BUF[t] = v;                                                 \
        __syncthreads();                                            \
        const float o_ = BUF[t ^ (J)];                              \
        const bool mn_ = (((t & (J)) == 0) == (UP));                \
        v = mn_ ? fminf(v, o_) : fmaxf(v, o_);                      \
    } while (0)

    SH(1, u2);
    SH(2, u4);  SH(1, u4);
    SH(4, u8);  SH(2, u8);  SH(1, u8);
    SH(8, u16); SH(4, u16); SH(2, u16); SH(1, u16);
    SH(16, u32); SH(8, u32); SH(4, u32); SH(2, u32); SH(1, u32);
    SMP(32, u64, sv);
    SH(16, u64); SH(8, u64); SH(4, u64); SH(2, u64); SH(1, u64);
    SMP(64, u128, sw); SMP(32, u128, sv);
    SH(16, u128); SH(8, u128); SH(4, u128); SH(2, u128); SH(1, u128);
    SMP(128, true, sw); SMP(64, true, sv); SMP(32, true, sw);
    SH(16, true); SH(8, true); SH(4, true); SH(2, true); SH(1, true);

#undef SH
#undef SMP

    float partial;
    if (diag) {
        partial = v * (float)(2 * t - 255);
    } else {
        // Inclusive prefix scan of sorted v.
        float x = v;
#pragma unroll
        for (int off = 1; off < 32; off <<= 1) {
            const float y = __shfl_up_sync(0xffffffffu, x, off);
            if (lane >= off) x += y;
        }
        if (lane == 31) red[wid] = x;
        __syncthreads();   // also fences the last SMP reads before sv reuse
        float woff = 0.0f;
#pragma unroll
        for (int w = 0; w < 8; ++w)
            woff += (w < wid) ? red[w] : 0.0f;

        sv[t]     = v;
        sp[t + 1] = x + woff;
        if (t == 0) sp[0] = 0.0f;
        __syncthreads();

        // Closed form (proven).
        const float k  = spac[c] * 2.0f;
        const float ds = (float)a * k - (float)b * k;  // reference rounding order
        const float c1 = 0.2f * ds;
        const float k1 = p - ds;
        const float k2 = p - c1;

        int cnt1 = 0, cnt2 = 0, cnt3 = 0;
#pragma unroll
        for (int s = 128; s > 0; s >>= 1) {
            cnt1 += (sv[cnt1 + s - 1] <  k1) ? s : 0;
            cnt2 += (sv[cnt2 + s - 1] <= k2) ? s : 0;
            cnt3 += (sv[cnt3 + s - 1] <= p ) ? s : 0;
        }
        cnt1 += (sv[cnt1] <  k1) ? 1 : 0;
        cnt2 += (sv[cnt2] <= k2) ? 1 : 0;
        cnt3 += (sv[cnt3] <= p ) ? 1 : 0;

        const float T = sp[256];
        partial = (float)cnt1 * k1 - sp[cnt1]
                + (T - sp[cnt2]) - (float)(256 - cnt2) * k2
                - c1 * (float)(256 - cnt3);
    }

    // ---- Block reduction of partial. ----
#pragma unroll
    for (int off = 16; off > 0; off >>= 1)
        partial += __shfl_xor_sync(0xffffffffu, partial, off);
    __syncthreads();
    if (lane == 0) red[wid] = partial;
    __syncthreads();

    if (t == 0) {
        const float tot = red[0] + red[1] + red[2] + red[3]
                        + red[4] + red[5] + red[6] + red[7];
        // Zero-kernel writes are long since visible; the wait is free here.
        cudaGridDependencySynchronize();
        atomicAdd(&out[c], tot * (1.0f / ((float)N_ELEM * (float)N_ELEM)));
    }
}

extern "C" void kernel_launch(void* const* d_in, const int* in_sizes, int n_in,
                              void* d_out, int out_size)
{
    (void)in_sizes; (void)n_in; (void)out_size;
    const float* pred = (const float*)d_in[0];
    const float* spac = (const float*)d_in[1];
    float* out = (float*)d_out;

    // Node 1: zero out[0..2]; triggers programmatic completion immediately.
    zero_out_kernel<<<1, 32>>>(out);

    // Node 2: fused kernel with PDL (launch overlaps node 1 entirely).
    cudaLaunchConfig_t cfg = {};
    cfg.gridDim  = dim3(NTASKS, 1, 1);
    cfg.blockDim = dim3(256, 1, 1);
    cfg.dynamicSmemBytes = 0;
    cudaLaunchAttribute attrs[1];
    attrs[0].id = cudaLaunchAttributeProgrammaticStreamSerialization;
    attrs[0].val.programmaticStreamSerializationAllowed = 1;
    cfg.attrs = attrs;
    cfg.numAttrs = 1;
    cudaLaunchKernelEx(&cfg, depthloss_fused, pred, spac, out);
}